// round 6
// baseline (speedup 1.0000x reference)
#include <cuda_runtime.h>
#include <math.h>

// Problem constants: B=16, K=16, N=1024, D=256, L=8
#define S_ELEMS (16*16*8*256)     // 524288  (S output [B,K,L,D])
// Beta output [B,K,L,N] follows S in d_out.

// ---------------- scratch (allocation-free __device__ globals) ----------------
__device__ __align__(16) float g_slots[128*256];       // [B*L, D]
__device__ __align__(16) float g_Mcomb[256*1024];      // [k][0:256]=Wq^T Wk * scale, [k][256:1024]=W_hh^T
__device__ __align__(16) float g_ccomb[1024];          // [0:256]=scale*bq@Wk, [256:1024]=b_hh
__device__ __align__(16) float g_M2[768*256];          // M2[c][j] = sum_d W_ih[c,d]*Wv[d,j]
__device__ __align__(16) float g_c2[768];              // W_ih@bv + b_ih
__device__ __align__(16) float g_qtgh[128*1024];       // cols 0:256 = Qtilde, 256:1024 = gh
__device__ __align__(16) float g_scores[128*1024];
__device__ __align__(16) float g_U[128*256];           // attn @ h_t
__device__ __align__(16) float g_gi[128*768];
__device__ __align__(16) float g_s2[128*256];
__device__ __align__(16) float g_h1[128*256];
__device__ __align__(16) float g_ffn[128*256];

// ================= generic 32x32-tile fp32 GEMM body =================
// C[m0+32 x c0+32] = A[M x Kd] @ B + bias.  BT=0: B is [Kd][ldb] row-major.
// BT=1: B is [Ncols][ldb] row-major (i.e. C = A @ B^T).
// 256 threads; each thread computes 1 row x 4 cols.
template<int BT, int RELU>
__device__ __forceinline__ void gemm_body(
    const float* __restrict__ A, int lda,
    const float* __restrict__ B, int ldb,
    const float* __restrict__ bias,
    float* __restrict__ C, int ldc, int Kd)
{
    __shared__ float As[32][33];
    __shared__ __align__(16) float Bs[32][36];
    const int tid = threadIdx.x;
    const int m0 = blockIdx.y * 32, c0 = blockIdx.x * 32;
    const int row = tid & 31, cg = tid >> 5;
    float a0 = 0.f, a1 = 0.f, a2 = 0.f, a3 = 0.f;

    for (int k0 = 0; k0 < Kd; k0 += 32) {
        {
            int e = tid & 31, r = tid >> 5;
            #pragma unroll
            for (int i = 0; i < 4; i++)
                As[r + i*8][e] = A[(size_t)(m0 + r + i*8) * lda + k0 + e];
        }
        if (BT) {
            int e = tid & 31, c = tid >> 5;
            #pragma unroll
            for (int i = 0; i < 4; i++) {
                int cc = c + i*8;
                Bs[e][cc] = B[(size_t)(c0 + cc) * ldb + k0 + e];
            }
        } else {
            int c = tid & 31, e = tid >> 5;
            #pragma unroll
            for (int i = 0; i < 4; i++) {
                int ee = e + i*8;
                Bs[ee][c] = B[(size_t)(k0 + ee) * ldb + c0 + c];
            }
        }
        __syncthreads();
        #pragma unroll
        for (int e = 0; e < 32; e++) {
            float a = As[row][e];
            float4 b4 = *(const float4*)&Bs[e][cg * 4];
            a0 = fmaf(a, b4.x, a0); a1 = fmaf(a, b4.y, a1);
            a2 = fmaf(a, b4.z, a2); a3 = fmaf(a, b4.w, a3);
        }
        __syncthreads();
    }
    int cb = c0 + cg * 4;
    float v0 = a0, v1 = a1, v2 = a2, v3 = a3;
    if (bias) { v0 += bias[cb]; v1 += bias[cb+1]; v2 += bias[cb+2]; v3 += bias[cb+3]; }
    if (RELU) { v0 = fmaxf(v0, 0.f); v1 = fmaxf(v1, 0.f); v2 = fmaxf(v2, 0.f); v3 = fmaxf(v3, 0.f); }
    *(float4*)&C[(size_t)(m0 + row) * ldc + cb] = make_float4(v0, v1, v2, v3);
}

// GEMM wrapper kernels (scratch referenced as device globals; no symbol-address needed)
__global__ void k_qtgh() {                       // [128 x 1024], K=256  grid(32,4)
    gemm_body<0,0>(g_slots, 256, g_Mcomb, 1024, g_ccomb, g_qtgh, 1024, 256);
}
__global__ void k_m2(const float* __restrict__ W_ih, const float* __restrict__ Wv) {
    // M2[c][j] = sum_d W_ih[c,d] * Wv[d,j]   [768 x 256], K=256  grid(8,24)
    gemm_body<0,0>(W_ih, 256, Wv, 256, nullptr, g_M2, 256, 256);
}
__global__ void k_gi() {                         // gi = U @ M2^T + c2  [128 x 768]  grid(24,4)
    gemm_body<1,0>(g_U, 256, g_M2, 256, g_c2, g_gi, 768, 256);
}
__global__ void k_ffn1(const float* __restrict__ W1, const float* __restrict__ b1) {
    gemm_body<1,1>(g_s2, 256, W1, 256, b1, g_h1, 256, 256);   // grid(8,4), relu
}
__global__ void k_ffn2(const float* __restrict__ W2, const float* __restrict__ b2) {
    gemm_body<1,0>(g_h1, 256, W2, 256, b2, g_ffn, 256, 256);  // grid(8,4)
}

// ================= precompute kernels =================
__global__ void init_slots_kernel(const float* __restrict__ eps,
                                  const float* __restrict__ mu,
                                  const float* __restrict__ ls)
{
    int i = blockIdx.x * 256 + threadIdx.x;      // 0..32767
    int ld = i & 2047;                           // L*D = 2048
    g_slots[i] = mu[ld] + expf(ls[ld]) * eps[i];
}

__global__ void m1_kernel(const float* __restrict__ Wq, const float* __restrict__ Wk)
{
    // Mcomb[i][j] = scale * sum_e Wq[e,i] * Wk[e,j]   (j<256)
    int j = blockIdx.x, i = threadIdx.x;
    float s = 0.f;
    #pragma unroll 4
    for (int e = 0; e < 256; e++)
        s = fmaf(Wq[e * 256 + i], Wk[e * 256 + j], s);
    g_Mcomb[i * 1024 + j] = s * 0.0625f;
}

__global__ void mhh_kernel(const float* __restrict__ W_hh)
{
    // Mcomb[k][256+c] = W_hh[c][k]
    int k = blockIdx.x;          // 0..255
    int c = threadIdx.x;         // 0..767
    g_Mcomb[k * 1024 + 256 + c] = W_hh[c * 256 + k];
}

__global__ void ccomb_kernel(const float* __restrict__ bq, const float* __restrict__ Wk,
                             const float* __restrict__ b_hh)
{
    int c = blockIdx.x * 256 + threadIdx.x;      // 0..1023
    if (c < 256) {
        float s = 0.f;
        #pragma unroll 4
        for (int e = 0; e < 256; e++) s = fmaf(bq[e], Wk[e * 256 + c], s);
        g_ccomb[c] = s * 0.0625f;
    } else {
        g_ccomb[c] = b_hh[c - 256];
    }
}

__global__ void c2_kernel(const float* __restrict__ W_ih, const float* __restrict__ bv,
                          const float* __restrict__ b_ih)
{
    int c = blockIdx.x * 256 + threadIdx.x;      // 0..767
    float s = b_ih[c];
    #pragma unroll 4
    for (int d = 0; d < 256; d++) s = fmaf(W_ih[c * 256 + d], bv[d], s);
    g_c2[c] = s;
}

// ================= per-step kernels =================
// scores[b*8+l][n] = sum_j Qt[b,l,j] * H[b,t,n,j]     grid(8,16), 256 thr
__global__ void scores_kernel(const float* __restrict__ H, int t)
{
    __shared__ float Qs[8][256];
    __shared__ float Hs[128][65];
    const int b = blockIdx.y;
    const int n0 = blockIdx.x * 128;
    const int tid = threadIdx.x;
    for (int i = tid; i < 2048; i += 256)
        Qs[i >> 8][i & 255] = g_qtgh[(b * 8 + (i >> 8)) * 1024 + (i & 255)];
    const float* hb = H + ((size_t)(b * 16 + t) * 1024 + n0) * 256;
    const int nl = tid & 127, half = tid >> 7;
    float a0 = 0.f, a1 = 0.f, a2 = 0.f, a3 = 0.f;
    for (int d0 = 0; d0 < 256; d0 += 64) {
        __syncthreads();
        {
            int c = tid & 63, r0 = tid >> 6;
            for (int rr = r0; rr < 128; rr += 4)
                Hs[rr][c] = hb[(size_t)rr * 256 + d0 + c];
        }
        __syncthreads();
        #pragma unroll 4
        for (int d = 0; d < 64; d++) {
            float hv = Hs[nl][d];
            a0 = fmaf(hv, Qs[half*4+0][d0+d], a0);
            a1 = fmaf(hv, Qs[half*4+1][d0+d], a1);
            a2 = fmaf(hv, Qs[half*4+2][d0+d], a2);
            a3 = fmaf(hv, Qs[half*4+3][d0+d], a3);
        }
    }
    g_scores[(b*8 + half*4+0)*1024 + n0 + nl] = a0;
    g_scores[(b*8 + half*4+1)*1024 + n0 + nl] = a1;
    g_scores[(b*8 + half*4+2)*1024 + n0 + nl] = a2;
    g_scores[(b*8 + half*4+3)*1024 + n0 + nl] = a3;
}

// softmax over n=1024; writes attn straight into Beta output.  grid(128), 256 thr
__global__ void softmax_kernel(float* __restrict__ beta, int t)
{
    const int r = blockIdx.x, tid = threadIdx.x;
    const float4 v = ((const float4*)(g_scores + (size_t)r * 1024))[tid];
    float m = fmaxf(fmaxf(v.x, v.y), fmaxf(v.z, v.w));
    #pragma unroll
    for (int o = 16; o > 0; o >>= 1) m = fmaxf(m, __shfl_xor_sync(0xffffffffu, m, o));
    __shared__ float red[8], red2[8];
    if ((tid & 31) == 0) red[tid >> 5] = m;
    __syncthreads();
    float mm = red[0];
    #pragma unroll
    for (int i = 1; i < 8; i++) mm = fmaxf(mm, red[i]);
    float e0 = expf(v.x - mm), e1 = expf(v.y - mm), e2 = expf(v.z - mm), e3 = expf(v.w - mm);
    float s = e0 + e1 + e2 + e3;
    #pragma unroll
    for (int o = 16; o > 0; o >>= 1) s += __shfl_xor_sync(0xffffffffu, s, o);
    if ((tid & 31) == 0) red2[tid >> 5] = s;
    __syncthreads();
    float ss = 0.f;
    #pragma unroll
    for (int i = 0; i < 8; i++) ss += red2[i];
    float inv = 1.f / ss;
    int b = r >> 3, l = r & 7;
    float* brow = beta + (size_t)((b * 16 + t) * 8 + l) * 1024;
    ((float4*)brow)[tid] = make_float4(e0 * inv, e1 * inv, e2 * inv, e3 * inv);
}

// U[b*8+l][j] = sum_n attn[b,l,n] * H[b,t,n,j]        grid(2,16), 256 thr
__global__ void u_kernel(const float* __restrict__ H, const float* __restrict__ beta, int t)
{
    __shared__ __align__(16) float As[8][1024];
    const int b = blockIdx.y;
    const int j0 = blockIdx.x * 128;
    const int tid = threadIdx.x;
    const float4* brow = (const float4*)(beta + (size_t)(b * 16 + t) * 8 * 1024);
    float4* As4 = (float4*)As;
    for (int i = tid; i < 2048; i += 256) As4[i] = brow[i];
    __syncthreads();
    const int jj = tid & 127, half = tid >> 7;
    const float* hb = H + (size_t)(b * 16 + t) * 1024 * 256 + j0 + jj;
    float a0 = 0.f, a1 = 0.f, a2 = 0.f, a3 = 0.f;
    #pragma unroll 4
    for (int n = 0; n < 1024; n++) {
        float hv = hb[(size_t)n * 256];
        a0 = fmaf(As[half*4+0][n], hv, a0);
        a1 = fmaf(As[half*4+1][n], hv, a1);
        a2 = fmaf(As[half*4+2][n], hv, a2);
        a3 = fmaf(As[half*4+3][n], hv, a3);
    }
    g_U[(b*8 + half*4+0)*256 + j0 + jj] = a0;
    g_U[(b*8 + half*4+1)*256 + j0 + jj] = a1;
    g_U[(b*8 + half*4+2)*256 + j0 + jj] = a2;
    g_U[(b*8 + half*4+3)*256 + j0 + jj] = a3;
}

// GRU elementwise: s2 = (1-z)*n + z*slots              grid(128), 256 thr
__global__ void gru_kernel()
{
    int idx = blockIdx.x * 256 + threadIdx.x;    // 0..32767
    int r = idx >> 8, d = idx & 255;
    float gir = g_gi[r*768 + d], giz = g_gi[r*768 + 256 + d], gin = g_gi[r*768 + 512 + d];
    float ghr = g_qtgh[r*1024 + 256 + d], ghz = g_qtgh[r*1024 + 512 + d], ghn = g_qtgh[r*1024 + 768 + d];
    float rg = 1.f / (1.f + expf(-(gir + ghr)));
    float z  = 1.f / (1.f + expf(-(giz + ghz)));
    float nn = tanhf(gin + rg * ghn);
    g_s2[idx] = (1.f - z) * nn + z * g_slots[idx];
}

// residual + LayerNorm; writes new slots and S output   grid(128), 256 thr
__global__ void ln_kernel(const float* __restrict__ lg, const float* __restrict__ lb,
                          float* __restrict__ outS, int t)
{
    const int r = blockIdx.x, d = threadIdx.x;
    float x = g_s2[r * 256 + d] + g_ffn[r * 256 + d];
    float s = x, q = x * x;
    #pragma unroll
    for (int o = 16; o > 0; o >>= 1) {
        s += __shfl_xor_sync(0xffffffffu, s, o);
        q += __shfl_xor_sync(0xffffffffu, q, o);
    }
    __shared__ float rs[8], rq[8];
    if ((d & 31) == 0) { rs[d >> 5] = s; rq[d >> 5] = q; }
    __syncthreads();
    float ts = 0.f, tq = 0.f;
    #pragma unroll
    for (int i = 0; i < 8; i++) { ts += rs[i]; tq += rq[i]; }
    float mean = ts * (1.f / 256.f);
    float var  = tq * (1.f / 256.f) - mean * mean;
    float inv  = rsqrtf(var + 1e-5f);
    float y = (x - mean) * inv * lg[d] + lb[d];
    g_slots[r * 256 + d] = y;
    int b = r >> 3, l = r & 7;
    outS[(size_t)((b * 16 + t) * 8 + l) * 256 + d] = y;
}

// ================= launcher =================
extern "C" void kernel_launch(void* const* d_in, const int* in_sizes, int n_in,
                              void* d_out, int out_size)
{
    const float* H    = (const float*)d_in[0];
    const float* eps  = (const float*)d_in[1];
    const float* mu   = (const float*)d_in[2];
    const float* ls   = (const float*)d_in[3];
    const float* Wq   = (const float*)d_in[4];
    const float* bq   = (const float*)d_in[5];
    const float* Wk   = (const float*)d_in[6];
    // d_in[7] = bk: provably cancels in softmax — unused.
    const float* Wv   = (const float*)d_in[8];
    const float* bv   = (const float*)d_in[9];
    const float* W_ih = (const float*)d_in[10];
    const float* b_ih = (const float*)d_in[11];
    const float* W_hh = (const float*)d_in[12];
    const float* b_hh = (const float*)d_in[13];
    const float* W1   = (const float*)d_in[14];
    const float* b1   = (const float*)d_in[15];
    const float* W2   = (const float*)d_in[16];
    const float* b2   = (const float*)d_in[17];
    const float* lng  = (const float*)d_in[18];
    const float* lnb  = (const float*)d_in[19];

    float* outS = (float*)d_out;
    float* outB = outS + S_ELEMS;

    // per-call precompute (deterministic, inside the graph)
    init_slots_kernel<<<128, 256>>>(eps, mu, ls);
    m1_kernel<<<256, 256>>>(Wq, Wk);
    mhh_kernel<<<256, 768>>>(W_hh);
    ccomb_kernel<<<4, 256>>>(bq, Wk, b_hh);
    k_m2<<<dim3(8, 24), 256>>>(W_ih, Wv);
    c2_kernel<<<3, 256>>>(W_ih, bv, b_ih);

    for (int t = 0; t < 16; t++) {
        k_qtgh<<<dim3(32, 4), 256>>>();
        scores_kernel<<<dim3(8, 16), 256>>>(H, t);
        softmax_kernel<<<128, 256>>>(outB, t);
        u_kernel<<<dim3(2, 16), 256>>>(H, outB, t);
        k_gi<<<dim3(24, 4), 256>>>();
        gru_kernel<<<128, 256>>>();
        k_ffn1<<<dim3(8, 4), 256>>>(W1, b1);
        k_ffn2<<<dim3(8, 4), 256>>>(W2, b2);
        ln_kernel<<<128, 256>>>(lng, lnb, outS, t);
    }
}

// round 7
// speedup vs baseline: 1.6639x; 1.6639x over previous
#include <cuda_runtime.h>
#include <math.h>

// Problem constants: B=16, K=16 steps, N=1024, D=256, L=8.  Rows = B*L = 128.
#define S_ELEMS (16*16*8*256)

// ---------------- scratch (allocation-free __device__ globals) ----------------
__device__ __align__(16) float g_slots[128*256];
__device__ __align__(16) float g_Mcomb[256*1024];   // [i][0:256]=Wq^T Wk*scale, [i][256:1024]=W_hh^T
__device__ __align__(16) float g_cpart[8*1024];     // 8 e-partials of [scale*bq@Wk | b_hh]
__device__ __align__(16) float g_M2[768*256];       // M2[c][j] = sum_d W_ih[c,d]*Wv[d,j]
__device__ __align__(16) float g_c2part[8*768];     // 8 e-partials of (W_ih@bv + b_ih)
__device__ __align__(16) float g_qtgh[128*1024];    // [row][0:256]=Qtilde, [256:1024]=gh
__device__ __align__(16) float g_scores[128*1024];
__device__ __align__(16) float g_pmax[128*8];       // per-row per-nchunk max
__device__ __align__(16) float g_psum[128*8];       // per-row per-nchunk sum of exp(x-chunkmax)
__device__ __align__(16) float g_upart[8*128*256];  // 8 n-chunk partials of attn@H
__device__ __align__(16) float g_gi[128*768];
__device__ __align__(16) float g_s2[128*256];
__device__ __align__(16) float g_h1[128*256];
__device__ __align__(16) float g_ffn[128*256];

__device__ __forceinline__ float sigm(float x) { return 1.f / (1.f + expf(-x)); }

// ================= generic 32x32-tile fp32 GEMM body =================
// AT: A is [Kd][lda] (use A^T).  BT=0: B is [Kd][ldb]; BT=1: B is [Ncols][ldb] (C=A@B^T).
// SUMA: sum that many A partials (stride strideA).  SUMB: 0 none, 1 plain, 8 partial-sum bias.
template<int AT, int BT, int RELU, int SUMA, int SUMB>
__device__ __forceinline__ void gemm_body(
    const float* __restrict__ A, int lda, int strideA,
    const float* __restrict__ B, int ldb,
    const float* __restrict__ bias, int strideBias,
    float* __restrict__ C, int ldc, int Kd, float alpha)
{
    __shared__ float As[32][33];
    __shared__ __align__(16) float Bs[32][36];
    const int tid = threadIdx.x;
    const int m0 = blockIdx.y * 32, c0 = blockIdx.x * 32;
    const int row = tid & 31, cg = tid >> 5;
    float a0 = 0.f, a1 = 0.f, a2 = 0.f, a3 = 0.f;

    for (int k0 = 0; k0 < Kd; k0 += 32) {
        if (AT) {
            int r = tid & 31, e = tid >> 5;
            #pragma unroll
            for (int i = 0; i < 4; i++) {
                int ee = e + i * 8;
                As[r][ee] = A[(size_t)(k0 + ee) * lda + m0 + r];
            }
        } else {
            int e = tid & 31, r = tid >> 5;
            #pragma unroll
            for (int i = 0; i < 4; i++) {
                int rr = r + i * 8;
                size_t idx = (size_t)(m0 + rr) * lda + k0 + e;
                float v = A[idx];
                if (SUMA == 8) {
                    #pragma unroll
                    for (int p = 1; p < 8; p++) v += A[idx + (size_t)p * strideA];
                }
                As[rr][e] = v;
            }
        }
        if (BT) {
            int e = tid & 31, c = tid >> 5;
            #pragma unroll
            for (int i = 0; i < 4; i++) {
                int cc = c + i * 8;
                Bs[e][cc] = B[(size_t)(c0 + cc) * ldb + k0 + e];
            }
        } else {
            int c = tid & 31, e = tid >> 5;
            #pragma unroll
            for (int i = 0; i < 4; i++) {
                int ee = e + i * 8;
                Bs[ee][c] = B[(size_t)(k0 + ee) * ldb + c0 + c];
            }
        }
        __syncthreads();
        #pragma unroll
        for (int e = 0; e < 32; e++) {
            float a = As[row][e];
            float4 b4 = *(const float4*)&Bs[e][cg * 4];
            a0 = fmaf(a, b4.x, a0); a1 = fmaf(a, b4.y, a1);
            a2 = fmaf(a, b4.z, a2); a3 = fmaf(a, b4.w, a3);
        }
        __syncthreads();
    }
    int cb = c0 + cg * 4;
    float v0 = a0 * alpha, v1 = a1 * alpha, v2 = a2 * alpha, v3 = a3 * alpha;
    if (SUMB == 1) {
        v0 += bias[cb]; v1 += bias[cb+1]; v2 += bias[cb+2]; v3 += bias[cb+3];
    } else if (SUMB == 8) {
        #pragma unroll
        for (int p = 0; p < 8; p++) {
            const float* bp = bias + (size_t)p * strideBias;
            v0 += bp[cb]; v1 += bp[cb+1]; v2 += bp[cb+2]; v3 += bp[cb+3];
        }
    }
    if (RELU) { v0 = fmaxf(v0,0.f); v1 = fmaxf(v1,0.f); v2 = fmaxf(v2,0.f); v3 = fmaxf(v3,0.f); }
    *(float4*)&C[(size_t)(m0 + row) * ldc + cb] = make_float4(v0, v1, v2, v3);
}

// ---- GEMM wrapper kernels ----
__global__ void k_qtgh() {                       // [128 x 1024] = slots @ Mcomb + ccomb   grid(32,4)
    gemm_body<0,0,0,1,8>(g_slots,256,0, g_Mcomb,1024, g_cpart,1024, g_qtgh,1024, 256, 1.f);
}
__global__ void k_m1(const float* __restrict__ Wq, const float* __restrict__ Wk) {
    // Mcomb[:, 0:256] = scale * Wq^T @ Wk     grid(8,8)
    gemm_body<1,0,0,1,0>(Wq,256,0, Wk,256, nullptr,0, g_Mcomb,1024, 256, 0.0625f);
}
__global__ void k_m2(const float* __restrict__ W_ih, const float* __restrict__ Wv) {
    // M2 = W_ih @ Wv   [768 x 256]            grid(8,24)
    gemm_body<0,0,0,1,0>(W_ih,256,0, Wv,256, nullptr,0, g_M2,256, 256, 1.f);
}
__global__ void k_gi() {                         // gi = (sum8 upart) @ M2^T + sum8 c2part  grid(24,4)
    gemm_body<0,1,0,8,8>(g_upart,256,128*256, g_M2,256, g_c2part,768, g_gi,768, 256, 1.f);
}
__global__ void k_ffn2(const float* __restrict__ W2, const float* __restrict__ b2) {
    gemm_body<0,1,0,1,1>(g_h1,256,0, W2,256, b2,0, g_ffn,256, 256, 1.f);   // grid(8,4)
}

// ================= precompute =================
__global__ void init_slots_kernel(const float* __restrict__ eps,
                                  const float* __restrict__ mu,
                                  const float* __restrict__ ls)
{
    int i = blockIdx.x * 256 + threadIdx.x;      // 0..32767
    int ld = i & 2047;
    g_slots[i] = mu[ld] + expf(ls[ld]) * eps[i];
}

__global__ void mhh_kernel(const float* __restrict__ W_hh)
{
    int k = blockIdx.x;          // 0..255
    int c = threadIdx.x;         // 0..767
    g_Mcomb[k * 1024 + 256 + c] = W_hh[c * 256 + k];
}

__global__ void ccomb_kernel(const float* __restrict__ bq, const float* __restrict__ Wk,
                             const float* __restrict__ b_hh)
{
    int p = blockIdx.x;                          // e-chunk 0..7
    int c = blockIdx.y * 256 + threadIdx.x;      // 0..1023
    if (c < 256) {
        int e0 = p * 32;
        float s = 0.f;
        #pragma unroll 8
        for (int e = 0; e < 32; e++) s = fmaf(bq[e0+e], Wk[(e0+e)*256 + c], s);
        g_cpart[p * 1024 + c] = s * 0.0625f;
    } else {
        g_cpart[p * 1024 + c] = (p == 0) ? b_hh[c - 256] : 0.f;
    }
}

__global__ void c2_kernel(const float* __restrict__ W_ih, const float* __restrict__ bv,
                          const float* __restrict__ b_ih)
{
    int p = blockIdx.x;                          // e-chunk 0..7
    int c = blockIdx.y * 256 + threadIdx.x;      // 0..767
    int e0 = p * 32;
    float s = (p == 0) ? b_ih[c] : 0.f;
    #pragma unroll 8
    for (int e = 0; e < 32; e++) s = fmaf(W_ih[c*256 + e0+e], bv[e0+e], s);
    g_c2part[p * 768 + c] = s;
}

// ================= per-step kernels =================
// scores + per-chunk softmax partials.  grid(8 nchunk, 16 b), 256 thr.
__global__ void scores_kernel(const float* __restrict__ H, int t)
{
    __shared__ __align__(16) float4 Qs4[8][64];      // Q [slot][d/4]
    __shared__ float Hs[128][68];                    // pitch 68: float4-aligned, conflict-free
    __shared__ float redM[8][4], redS[8][4], mrow[8];
    const int b = blockIdx.y, chunk = blockIdx.x;
    const int n0 = chunk * 128;
    const int tid = threadIdx.x;
    const int nl = tid & 127, half = tid >> 7;
    const int lane = tid & 31, wId = tid >> 5;

    for (int i = tid; i < 512; i += 256)
        Qs4[i >> 6][i & 63] = ((const float4*)(g_qtgh + (size_t)(b*8 + (i>>6)) * 1024))[i & 63];

    const float* hb = H + ((size_t)(b * 16 + t) * 1024 + n0) * 256;
    float a[4] = {0.f, 0.f, 0.f, 0.f};

    for (int d0 = 0; d0 < 256; d0 += 64) {
        __syncthreads();
        {
            int c = tid & 63, r0 = tid >> 6;
            #pragma unroll
            for (int i = 0; i < 32; i++)
                Hs[r0 + i*4][c] = hb[(size_t)(r0 + i*4) * 256 + d0 + c];
        }
        __syncthreads();
        #pragma unroll
        for (int d = 0; d < 64; d += 4) {
            float4 h4 = *(const float4*)&Hs[nl][d];
            int qd = (d0 + d) >> 2;
            #pragma unroll
            for (int s = 0; s < 4; s++) {
                float4 q4 = Qs4[half*4 + s][qd];
                a[s] = fmaf(h4.x, q4.x, a[s]); a[s] = fmaf(h4.y, q4.y, a[s]);
                a[s] = fmaf(h4.z, q4.z, a[s]); a[s] = fmaf(h4.w, q4.w, a[s]);
            }
        }
    }
    #pragma unroll
    for (int s = 0; s < 4; s++)
        g_scores[(size_t)(b*8 + half*4 + s) * 1024 + n0 + nl] = a[s];

    // per-chunk max
    #pragma unroll
    for (int s = 0; s < 4; s++) {
        float m = a[s];
        #pragma unroll
        for (int o = 16; o > 0; o >>= 1) m = fmaxf(m, __shfl_xor_sync(0xffffffffu, m, o));
        if (lane == 0) redM[half*4 + s][wId & 3] = m;
    }
    __syncthreads();
    if (tid < 8) {
        float m = fmaxf(fmaxf(redM[tid][0], redM[tid][1]), fmaxf(redM[tid][2], redM[tid][3]));
        mrow[tid] = m;
        g_pmax[(b*8 + tid) * 8 + chunk] = m;
    }
    __syncthreads();
    // per-chunk sum of exp(x - chunkmax)
    #pragma unroll
    for (int s = 0; s < 4; s++) {
        float e = expf(a[s] - mrow[half*4 + s]);
        #pragma unroll
        for (int o = 16; o > 0; o >>= 1) e += __shfl_xor_sync(0xffffffffu, e, o);
        if (lane == 0) redS[half*4 + s][wId & 3] = e;
    }
    __syncthreads();
    if (tid < 8)
        g_psum[(b*8 + tid) * 8 + chunk] = redS[tid][0] + redS[tid][1] + redS[tid][2] + redS[tid][3];
}

// attn (on-the-fly softmax) + Beta write + partial attn@H.  grid(8 nchunk, 16 b, 2 jhalf), 256 thr.
__global__ void u_kernel(const float* __restrict__ H, float* __restrict__ beta, int t)
{
    __shared__ float attn[8][128];
    __shared__ float mrow[8], invS[8];
    const int b = blockIdx.y, nc = blockIdx.x;
    const int n0 = nc * 128, j0 = blockIdx.z * 128;
    const int tid = threadIdx.x;

    if (tid < 8) {
        int r = b * 8 + tid;
        float m = g_pmax[r*8];
        #pragma unroll
        for (int c = 1; c < 8; c++) m = fmaxf(m, g_pmax[r*8 + c]);
        float S = 0.f;
        #pragma unroll
        for (int c = 0; c < 8; c++) S += g_psum[r*8 + c] * expf(g_pmax[r*8 + c] - m);
        mrow[tid] = m; invS[tid] = 1.f / S;
    }
    __syncthreads();
    for (int i = tid; i < 1024; i += 256) {
        int s = i >> 7, n = i & 127;
        float aa = expf(g_scores[(size_t)(b*8 + s) * 1024 + n0 + n] - mrow[s]) * invS[s];
        attn[s][n] = aa;
        if (blockIdx.z == 0)
            beta[(size_t)((b*16 + t) * 8 + s) * 1024 + n0 + n] = aa;
    }
    __syncthreads();

    const int jj = tid & 127, sg = tid >> 7;
    const float* hb = H + ((size_t)(b * 16 + t) * 1024 + n0) * 256 + j0 + jj;
    float a0 = 0.f, a1 = 0.f, a2 = 0.f, a3 = 0.f;
    #pragma unroll 8
    for (int n = 0; n < 128; n++) {
        float hv = hb[(size_t)n * 256];
        a0 = fmaf(attn[sg*4+0][n], hv, a0);
        a1 = fmaf(attn[sg*4+1][n], hv, a1);
        a2 = fmaf(attn[sg*4+2][n], hv, a2);
        a3 = fmaf(attn[sg*4+3][n], hv, a3);
    }
    float* up = g_upart + (size_t)nc * 128 * 256;
    up[(b*8 + sg*4 + 0) * 256 + j0 + jj] = a0;
    up[(b*8 + sg*4 + 1) * 256 + j0 + jj] = a1;
    up[(b*8 + sg*4 + 2) * 256 + j0 + jj] = a2;
    up[(b*8 + sg*4 + 3) * 256 + j0 + jj] = a3;
}

// ffn1 with fused GRU: A-tile = s2 computed from gi/gh/slots; h1 = relu(s2@W1^T + b1).
// blockIdx.x==0 blocks materialize s2 for the LN residual.  grid(8,4), 256 thr.
__global__ void ffn1_gru_kernel(const float* __restrict__ W1, const float* __restrict__ b1)
{
    __shared__ float As[32][33];
    __shared__ __align__(16) float Bs[32][36];
    const int tid = threadIdx.x;
    const int m0 = blockIdx.y * 32, c0 = blockIdx.x * 32;
    const int row = tid & 31, cg = tid >> 5;
    float a0 = 0.f, a1 = 0.f, a2 = 0.f, a3 = 0.f;

    for (int k0 = 0; k0 < 256; k0 += 32) {
        {
            int e = tid & 31, r = tid >> 5;
            #pragma unroll
            for (int i = 0; i < 4; i++) {
                int rr = r + i * 8;
                int g = m0 + rr, d = k0 + e;
                float gir = g_gi[g*768 + d], giz = g_gi[g*768 + 256 + d], gin = g_gi[g*768 + 512 + d];
                float ghr = g_qtgh[g*1024 + 256 + d], ghz = g_qtgh[g*1024 + 512 + d], ghn = g_qtgh[g*1024 + 768 + d];
                float rg = sigm(gir + ghr);
                float z  = sigm(giz + ghz);
                float nn = tanhf(gin + rg * ghn);
                float s2 = (1.f - z) * nn + z * g_slots[g*256 + d];
                As[rr][e] = s2;
                if (blockIdx.x == 0) g_s2[g*256 + d] = s2;
            }
        }
        {
            int e = tid & 31, c = tid >> 5;
            #pragma unroll
            for (int i = 0; i < 4; i++) {
                int cc = c + i * 8;
                Bs[e][cc] = W1[(size_t)(c0 + cc) * 256 + k0 + e];
            }
        }
        __syncthreads();
        #pragma unroll
        for (int e = 0; e < 32; e++) {
            float a = As[row][e];
            float4 b4 = *(const float4*)&Bs[e][cg * 4];
            a0 = fmaf(a, b4.x, a0); a1 = fmaf(a, b4.y, a1);
            a2 = fmaf(a, b4.z, a2); a3 = fmaf(a, b4.w, a3);
        }
        __syncthreads();
    }
    int cb = c0 + cg * 4;
    float v0 = fmaxf(a0 + b1[cb],   0.f);
    float v1 = fmaxf(a1 + b1[cb+1], 0.f);
    float v2 = fmaxf(a2 + b1[cb+2], 0.f);
    float v3 = fmaxf(a3 + b1[cb+3], 0.f);
    *(float4*)&g_h1[(size_t)(m0 + row) * 256 + cb] = make_float4(v0, v1, v2, v3);
}

// residual + LayerNorm; writes new slots and S output.  grid(128), 256 thr.
__global__ void ln_kernel(const float* __restrict__ lg, const float* __restrict__ lb,
                          float* __restrict__ outS, int t)
{
    const int r = blockIdx.x, d = threadIdx.x;
    float x = g_s2[r * 256 + d] + g_ffn[r * 256 + d];
    float s = x, q = x * x;
    #pragma unroll
    for (int o = 16; o > 0; o >>= 1) {
        s += __shfl_xor_sync(0xffffffffu, s, o);
        q += __shfl_xor_sync(0xffffffffu, q, o);
    }
    __shared__ float rs[8], rq[8];
    if ((d & 31) == 0) { rs[d >> 5] = s; rq[d >> 5] = q; }
    __syncthreads();
    float ts = 0.f, tq = 0.f;
    #pragma unroll
    for (int i = 0; i < 8; i++) { ts += rs[i]; tq += rq[i]; }
    float mean = ts * (1.f / 256.f);
    float var  = tq * (1.f / 256.f) - mean * mean;
    float inv  = rsqrtf(var + 1e-5f);
    float y = (x - mean) * inv * lg[d] + lb[d];
    g_slots[r * 256 + d] = y;
    int b = r >> 3, l = r & 7;
    outS[(size_t)((b * 16 + t) * 8 + l) * 256 + d] = y;
}

// ================= launcher =================
extern "C" void kernel_launch(void* const* d_in, const int* in_sizes, int n_in,
                              void* d_out, int out_size)
{
    const float* H    = (const float*)d_in[0];
    const float* eps  = (const float*)d_in[1];
    const float* mu   = (const float*)d_in[2];
    const float* ls   = (const float*)d_in[3];
    const float* Wq   = (const float*)d_in[4];
    const float* bq   = (const float*)d_in[5];
    const float* Wk   = (const float*)d_in[6];
    // d_in[7] = bk: cancels in softmax (row-constant) — provably unused.
    const float* Wv   = (const float*)d_in[8];
    const float* bv   = (const float*)d_in[9];
    const float* W_ih = (const float*)d_in[10];
    const float* b_ih = (const float*)d_in[11];
    const float* W_hh = (const float*)d_in[12];
    const float* b_hh = (const float*)d_in[13];
    const float* W1   = (const float*)d_in[14];
    const float* b1   = (const float*)d_in[15];
    const float* W2   = (const float*)d_in[16];
    const float* b2   = (const float*)d_in[17];
    const float* lng  = (const float*)d_in[18];
    const float* lnb  = (const float*)d_in[19];

    float* outS = (float*)d_out;
    float* outB = outS + S_ELEMS;

    init_slots_kernel<<<128, 256>>>(eps, mu, ls);
    k_m1<<<dim3(8, 8), 256>>>(Wq, Wk);
    mhh_kernel<<<256, 768>>>(W_hh);
    ccomb_kernel<<<dim3(8, 4), 256>>>(bq, Wk, b_hh);
    k_m2<<<dim3(8, 24), 256>>>(W_ih, Wv);
    c2_kernel<<<dim3(8, 3), 256>>>(W_ih, bv, b_ih);

    for (int t = 0; t < 16; t++) {
        k_qtgh<<<dim3(32, 4), 256>>>();
        scores_kernel<<<dim3(8, 16), 256>>>(H, t);
        u_kernel<<<dim3(8, 16, 2), 256>>>(H, outB, t);
        k_gi<<<dim3(24, 4), 256>>>();
        ffn1_gru_kernel<<<dim3(8, 4), 256>>>(W1, b1);
        k_ffn2<<<dim3(8, 4), 256>>>(W2, b2);
        ln_kernel<<<128, 256>>>(lng, lnb, outS, t);
    }
}